// round 1
// baseline (speedup 1.0000x reference)
#include <cuda_runtime.h>
#include <cuda_bf16.h>

#define B_ 8
#define C_ 1024
#define T_ 2048
#define S_ 2048
#define E_ 1024

// Scratch (allocation-free rule: __device__ globals)
__device__ float g_comb[(size_t)B_ * T_ * E_];  // (conved_emb + x) * scale  [B,T,E]
__device__ float g_att [(size_t)B_ * T_ * E_];  // attended                  [B,T,E]

// ---------------------------------------------------------------------------
// Generic strided tiled SGEMM: C[m,n] = sum_k A(m,k) * B(k,n)
//   AMODE 0: A addr = k*lda + m   (m contiguous)
//   AMODE 1: A addr = m*lda + k   (k contiguous)
//   BMODE 0: B addr = k*ldb + n   (n contiguous)
//   BMODE 1: B addr = n*ldb + k   (k contiguous)
// Block tile 128x128, K-tile 8, 256 threads, 8x8 per-thread microtile.
// Requires M,N % 128 == 0, K % 8 == 0 (true for all stages here).
// ---------------------------------------------------------------------------
#define BM 128
#define BN 128
#define BK 8

template <int AMODE, int BMODE, class Epi>
__global__ __launch_bounds__(256) void gemm_kernel(
    const float* __restrict__ Abase, long strideAb,
    const float* __restrict__ Bbase, long strideBb,
    int K, int lda, int ldb, Epi epi)
{
    __shared__ float As[BK][BM];
    __shared__ float Bs[BK][BN];

    const int b   = blockIdx.z;
    const float* A = Abase + (long)b * strideAb;
    const float* Bm = Bbase + (long)b * strideBb;
    const int m0 = blockIdx.x * BM;
    const int n0 = blockIdx.y * BN;
    const int tid = threadIdx.x;
    const int tx = tid & 15;
    const int ty = tid >> 4;

    float acc[8][8];
#pragma unroll
    for (int i = 0; i < 8; i++)
#pragma unroll
        for (int j = 0; j < 8; j++) acc[i][j] = 0.f;

    for (int k0 = 0; k0 < K; k0 += BK) {
        // ---- load A tile into As[k][m] ----
        if (AMODE == 0) {
#pragma unroll
            for (int i = 0; i < 4; i++) {
                int idx = tid + i * 256;
                int k = idx >> 7, m = idx & 127;
                As[k][m] = A[(long)(k0 + k) * lda + (m0 + m)];
            }
        } else {
#pragma unroll
            for (int i = 0; i < 4; i++) {
                int idx = tid + i * 256;
                int m = idx >> 3, k = idx & 7;
                As[k][m] = A[(long)(m0 + m) * lda + (k0 + k)];
            }
        }
        // ---- load B tile into Bs[k][n] ----
        if (BMODE == 0) {
#pragma unroll
            for (int i = 0; i < 4; i++) {
                int idx = tid + i * 256;
                int k = idx >> 7, n = idx & 127;
                Bs[k][n] = Bm[(long)(k0 + k) * ldb + (n0 + n)];
            }
        } else {
#pragma unroll
            for (int i = 0; i < 4; i++) {
                int idx = tid + i * 256;
                int n = idx >> 3, k = idx & 7;
                Bs[k][n] = Bm[(long)(n0 + n) * ldb + (k0 + k)];
            }
        }
        __syncthreads();

#pragma unroll
        for (int kk = 0; kk < BK; kk++) {
            float4 a0 = *(const float4*)&As[kk][ty * 4];
            float4 a1 = *(const float4*)&As[kk][64 + ty * 4];
            float4 b0 = *(const float4*)&Bs[kk][tx * 4];
            float4 b1 = *(const float4*)&Bs[kk][64 + tx * 4];
            float ar[8] = {a0.x, a0.y, a0.z, a0.w, a1.x, a1.y, a1.z, a1.w};
            float br[8] = {b0.x, b0.y, b0.z, b0.w, b1.x, b1.y, b1.z, b1.w};
#pragma unroll
            for (int i = 0; i < 8; i++)
#pragma unroll
                for (int j = 0; j < 8; j++) acc[i][j] += ar[i] * br[j];
        }
        __syncthreads();
    }

    // ---- epilogue ----
#pragma unroll
    for (int i = 0; i < 8; i++) {
        int m = m0 + (i < 4 ? ty * 4 + i : 64 + ty * 4 + (i - 4));
#pragma unroll
        for (int j = 0; j < 8; j++) {
            int n = n0 + (j < 4 ? tx * 4 + j : 64 + tx * 4 + (j - 4));
            epi(b, m, n, acc[i][j]);
        }
    }
}

// ---- epilogues ----------------------------------------------------------
struct EpiComb {  // g_comb = (emb + b_h2e + x) * scale
    const float* bias; const float* x; const float* scale; float* out;
    __device__ void operator()(int b, int m, int n, float v) const {
        long o = ((long)b * T_ + m) * E_ + n;
        out[o] = (v + bias[n] + x[o]) * scale[0];
    }
};
struct EpiStore {  // plain row-major store, row length ldc
    float* out; int ldc; long strideB;
    __device__ void operator()(int b, int m, int n, float v) const {
        out[(long)b * strideB + (long)m * ldc + n] = v;
    }
};
struct EpiOutProj {  // out2[b,c,t] = v + b_e2h[c] + conved[b,c,t]   (n = c, m = t)
    const float* bias; const float* conved; float* out;
    __device__ void operator()(int b, int m, int n, float v) const {
        long o = ((long)b * C_ + n) * T_ + m;
        out[o] = v + bias[n] + conved[o];
    }
};

// ---- softmax over last dim (S_=2048), in place, one block per row -------
__global__ __launch_bounds__(256) void softmax_kernel(float* __restrict__ att)
{
    float* p = att + (long)blockIdx.x * S_;
    const int tid = threadIdx.x;
    __shared__ float red[8];

    float v[8];
    float mx = -1e30f;
#pragma unroll
    for (int i = 0; i < 8; i++) {
        v[i] = p[tid + i * 256];
        mx = fmaxf(mx, v[i]);
    }
#pragma unroll
    for (int o = 16; o; o >>= 1) mx = fmaxf(mx, __shfl_xor_sync(0xffffffffu, mx, o));
    if ((tid & 31) == 0) red[tid >> 5] = mx;
    __syncthreads();
    float bm = red[0];
#pragma unroll
    for (int w = 1; w < 8; w++) bm = fmaxf(bm, red[w]);
    __syncthreads();

    float sum = 0.f;
#pragma unroll
    for (int i = 0; i < 8; i++) {
        v[i] = __expf(v[i] - bm);
        sum += v[i];
    }
#pragma unroll
    for (int o = 16; o; o >>= 1) sum += __shfl_xor_sync(0xffffffffu, sum, o);
    if ((tid & 31) == 0) red[tid >> 5] = sum;
    __syncthreads();
    float bs = 0.f;
#pragma unroll
    for (int w = 0; w < 8; w++) bs += red[w];
    float inv = 1.f / bs;
#pragma unroll
    for (int i = 0; i < 8; i++) p[tid + i * 256] = v[i] * inv;
}

// ---------------------------------------------------------------------------
extern "C" void kernel_launch(void* const* d_in, const int* in_sizes, int n_in,
                              void* d_out, int out_size)
{
    (void)in_sizes; (void)n_in; (void)out_size;
    const float* conved       = (const float*)d_in[0];  // [B,C,T]
    const float* enc_conved   = (const float*)d_in[1];  // [B,S,E]
    const float* enc_combined = (const float*)d_in[2];  // [B,S,E]
    const float* x            = (const float*)d_in[3];  // [B,T,E]
    const float* scale        = (const float*)d_in[4];  // scalar
    const float* W_h2e        = (const float*)d_in[5];  // [E,C]
    const float* b_h2e        = (const float*)d_in[6];  // [E]
    const float* W_e2h        = (const float*)d_in[7];  // [C,E]
    const float* b_e2h        = (const float*)d_in[8];  // [C]

    float* attn = (float*)d_out;                               // [B,T,S]
    float* out2 = (float*)d_out + (long)B_ * T_ * S_;          // [B,C,T]

    float *comb, *attd;
    cudaGetSymbolAddress((void**)&comb, g_comb);
    cudaGetSymbolAddress((void**)&attd, g_att);

    dim3 blk(256);

    // Stage 1: conved_comb[b,t,e] = (conved^T @ W_h2e^T + b + x) * scale
    //   A(m=t,k=c) = conved[b, c, t]  -> AMODE 0, lda=T
    //   B(k=c,n=e) = W_h2e[e, c]      -> BMODE 1, ldb=C
    gemm_kernel<0, 1, EpiComb><<<dim3(T_ / BM, E_ / BN, B_), blk>>>(
        conved, (long)C_ * T_, W_h2e, 0L, C_, T_, C_,
        EpiComb{b_h2e, x, scale, comb});

    // Stage 2: energy[b,t,s] = comb @ enc_conved^T
    //   A(m=t,k=e) row-major -> AMODE 1, lda=E
    //   B(k=e,n=s) = enc_conved[b,s,e] -> BMODE 1, ldb=E
    gemm_kernel<1, 1, EpiStore><<<dim3(T_ / BM, S_ / BN, B_), blk>>>(
        comb, (long)T_ * E_, enc_conved, (long)S_ * E_, E_, E_, E_,
        EpiStore{attn, S_, (long)T_ * S_});

    // Stage 3: softmax over S, in place in d_out
    softmax_kernel<<<B_ * T_, blk>>>(attn);

    // Stage 4: attended[b,t,e] = attn @ enc_combined
    //   A(m=t,k=s) row-major -> AMODE 1, lda=S
    //   B(k=s,n=e) row-major -> BMODE 0, ldb=E
    gemm_kernel<1, 0, EpiStore><<<dim3(T_ / BM, E_ / BN, B_), blk>>>(
        attn, (long)T_ * S_, enc_combined, (long)S_ * E_, S_, S_, E_,
        EpiStore{attd, E_, (long)T_ * E_});

    // Stage 5: out2[b,c,t] = attended @ W_e2h^T + b_e2h + conved  (transposed store)
    //   A(m=t,k=e) row-major -> AMODE 1, lda=E
    //   B(k=e,n=c) = W_e2h[c,e] -> BMODE 1, ldb=E
    gemm_kernel<1, 1, EpiOutProj><<<dim3(T_ / BM, C_ / BN, B_), blk>>>(
        attd, (long)T_ * E_, W_e2h, 0L, E_, E_, E_,
        EpiOutProj{b_e2h, conved, out2});
}

// round 4
// speedup vs baseline: 2.8010x; 2.8010x over previous
#include <cuda_runtime.h>
#include <cuda_bf16.h>
#include <cstdint>

#define B_ 8
#define C_ 1024
#define T_ 2048
#define S_ 2048
#define E_ 1024

typedef __nv_bfloat16 bf16;

// ---------------- scratch (__device__ globals: allocation-free rule) -------
__device__ bf16 g_convT_h[(size_t)B_*T_*C_];
__device__ bf16 g_convT_l[(size_t)B_*T_*C_];
__device__ bf16 g_wh2e_h[(size_t)E_*C_];
__device__ bf16 g_wh2e_l[(size_t)E_*C_];
__device__ bf16 g_encK_h[(size_t)B_*S_*E_];
__device__ bf16 g_encK_l[(size_t)B_*S_*E_];
__device__ bf16 g_comb_h[(size_t)B_*T_*E_];
__device__ bf16 g_comb_l[(size_t)B_*T_*E_];
__device__ bf16 g_attn_h[(size_t)B_*T_*S_];
__device__ bf16 g_attn_l[(size_t)B_*T_*S_];
__device__ bf16 g_encVT_h[(size_t)B_*E_*S_];
__device__ bf16 g_encVT_l[(size_t)B_*E_*S_];
__device__ bf16 g_attd_h[(size_t)B_*T_*E_];
__device__ bf16 g_attd_l[(size_t)B_*T_*E_];
__device__ bf16 g_we2h_h[(size_t)C_*E_];
__device__ bf16 g_we2h_l[(size_t)C_*E_];

// ---------------- helpers ----------------------------------------------------
__device__ __forceinline__ uint32_t smem_u32(const void* p) {
    uint32_t a;
    asm("{ .reg .u64 t; cvta.to.shared.u64 t, %1; cvt.u32.u64 %0, t; }"
        : "=r"(a) : "l"(p));
    return a;
}
__device__ __forceinline__ void cp16(uint32_t dst, const void* src) {
    asm volatile("cp.async.cg.shared.global [%0], [%1], 16;"
                 :: "r"(dst), "l"(src) : "memory");
}
__device__ __forceinline__ void ldsm4(uint32_t* r, uint32_t a) {
    asm volatile("ldmatrix.sync.aligned.m8n8.x4.shared.b16 {%0,%1,%2,%3}, [%4];"
        : "=r"(r[0]), "=r"(r[1]), "=r"(r[2]), "=r"(r[3]) : "r"(a));
}
__device__ __forceinline__ void mma16816(float* d, const uint32_t* a, const uint32_t* b) {
    asm volatile("mma.sync.aligned.m16n8k16.row.col.f32.bf16.bf16.f32 "
        "{%0,%1,%2,%3}, {%4,%5,%6,%7}, {%8,%9}, {%0,%1,%2,%3};"
        : "+f"(d[0]), "+f"(d[1]), "+f"(d[2]), "+f"(d[3])
        : "r"(a[0]), "r"(a[1]), "r"(a[2]), "r"(a[3]), "r"(b[0]), "r"(b[1]));
}
__device__ __forceinline__ uint32_t sw(uint32_t bo) {  // SW128 swizzle
    return bo ^ ((bo >> 3) & 0x70);
}

#define TILE_SZ 16384            // 128 rows x 64 bf16 (128B) per tile
#define SMEM_BYTES (1024 + 2 * 4 * TILE_SZ)   // pad + 2 bufs x 4 tiles

// async-load one 128x64 bf16 tile (k-contiguous source) into swizzled smem
__device__ __forceinline__ void load_tile_async(const bf16* __restrict__ src,
                                                int row0, int ld, int k0,
                                                uint32_t sdst, int tid) {
#pragma unroll
    for (int r = 0; r < 4; r++) {
        int c = tid + r * 256;
        int row = c >> 3, seg = c & 7;
        uint32_t bo = (uint32_t)(row * 128 + seg * 16);
        cp16(sdst + sw(bo), src + (size_t)(row0 + row) * ld + k0 + seg * 8);
    }
}

// ---------------- GEMM args --------------------------------------------------
struct GemmArgs {
    const bf16 *Ah, *Al, *Bh, *Bl;
    long sA, sB;
    int lda, ldb, nChunks;
    float* outF;
    bf16 *outH, *outL;
    const float *bias, *xres, *scale, *conved;
};

// MODE: 0 comb (bias+x,*scale -> bf16 hi/lo), 1 energy (fp32),
//       2 attd (bf16 hi/lo), 3 outproj (transposed +bias+residual fp32)
template <int MODE>
__global__ __launch_bounds__(256, 1) void mma_gemm(GemmArgs g) {
    extern __shared__ char sraw[];
    uint32_t sb0 = smem_u32(sraw);
    uint32_t sbase = (sb0 + 1023) & ~1023u;
    char* sgen = sraw + (sbase - sb0);

    const int tid = threadIdx.x;
    const int m0 = blockIdx.x * 128, n0 = blockIdx.y * 128, b = blockIdx.z;
    const uint32_t BUF = 4 * TILE_SZ;

    const bf16* Ah = g.Ah + (size_t)b * g.sA;
    const bf16* Al = g.Al + (size_t)b * g.sA;
    const bf16* Bh = g.Bh + (size_t)b * g.sB;
    const bf16* Bl = g.Bl + (size_t)b * g.sB;

    const int wid = tid >> 5, lane = tid & 31;
    const int wm = (wid & 1) * 64, wn = (wid >> 1) * 32;

    float acc[4][4][4];
#pragma unroll
    for (int i = 0; i < 4; i++)
#pragma unroll
        for (int j = 0; j < 4; j++)
#pragma unroll
            for (int k = 0; k < 4; k++) acc[i][j][k] = 0.f;

    auto load = [&](int i) {
        int k0 = i * 64;
        uint32_t off = sbase + (uint32_t)(i & 1) * BUF;
        load_tile_async(Ah, m0, g.lda, k0, off,               tid);
        load_tile_async(Al, m0, g.lda, k0, off + TILE_SZ,     tid);
        load_tile_async(Bh, n0, g.ldb, k0, off + 2 * TILE_SZ, tid);
        load_tile_async(Bl, n0, g.ldb, k0, off + 3 * TILE_SZ, tid);
        asm volatile("cp.async.commit_group;" ::: "memory");
    };

    // ldmatrix x4 offsets (swizzled), NON-transposed for both A and B:
    // A: 16x16 tile at (wm+mt*16, ks*16): lanes 0-7 rows0-7/k0, 8-15 rows8-15/k0,
    //    16-23 rows0-7/k8, 24-31 rows8-15/k8  -> {a0,a1,a2,a3}
    uint32_t aoff[4][4], boff[2][4];
#pragma unroll
    for (int mt = 0; mt < 4; mt++)
#pragma unroll
        for (int ks = 0; ks < 4; ks++)
            aoff[mt][ks] = sw((uint32_t)((wm + mt * 16 + (lane & 15)) * 128 +
                                          ks * 32 + (lane >> 4) * 16));
    // B: 16(n)x16(k) block at (wn+np*16, ks*16): m0=n0-7/k0-7, m1=n0-7/k8-15,
    //    m2=n8-15/k0-7, m3=n8-15/k8-15
#pragma unroll
    for (int np = 0; np < 2; np++)
#pragma unroll
        for (int ks = 0; ks < 4; ks++)
            boff[np][ks] = sw((uint32_t)((wn + np * 16 + (lane & 7) + (lane >> 4) * 8) * 128 +
                                          ks * 32 + ((lane >> 3) & 1) * 16));

    load(0);
    const int nch = g.nChunks;
    for (int i = 0; i < nch; i++) {
        if (i + 1 < nch) {
            load(i + 1);
            asm volatile("cp.async.wait_group 1;" ::: "memory");
        } else {
            asm volatile("cp.async.wait_group 0;" ::: "memory");
        }
        __syncthreads();

        uint32_t base = sbase + (uint32_t)(i & 1) * BUF;
        uint32_t aHp = base, aLp = base + TILE_SZ;
        uint32_t bHp = base + 2 * TILE_SZ, bLp = base + 3 * TILE_SZ;

#pragma unroll
        for (int ks = 0; ks < 4; ks++) {
            uint32_t Ahr[4][4], Alr[4][4], Bhr[4][2], Blr[4][2];
#pragma unroll
            for (int mt = 0; mt < 4; mt++) {
                ldsm4(Ahr[mt], aHp + aoff[mt][ks]);
                ldsm4(Alr[mt], aLp + aoff[mt][ks]);
            }
#pragma unroll
            for (int np = 0; np < 2; np++) {
                uint32_t q[4];
                ldsm4(q, bHp + boff[np][ks]);
                Bhr[np * 2][0] = q[0]; Bhr[np * 2][1] = q[1];
                Bhr[np * 2 + 1][0] = q[2]; Bhr[np * 2 + 1][1] = q[3];
                ldsm4(q, bLp + boff[np][ks]);
                Blr[np * 2][0] = q[0]; Blr[np * 2][1] = q[1];
                Blr[np * 2 + 1][0] = q[2]; Blr[np * 2 + 1][1] = q[3];
            }
#pragma unroll
            for (int mt = 0; mt < 4; mt++)
#pragma unroll
                for (int nt = 0; nt < 4; nt++) {
                    mma16816(acc[mt][nt], Ahr[mt], Bhr[nt]);
                    mma16816(acc[mt][nt], Ahr[mt], Blr[nt]);
                    mma16816(acc[mt][nt], Alr[mt], Bhr[nt]);
                }
        }
        __syncthreads();
    }

    // ---- epilogue: stage through smem for coalesced writes ----
    float* stg = (float*)sgen;   // 128 x 132
#pragma unroll
    for (int mt = 0; mt < 4; mt++)
#pragma unroll
        for (int nt = 0; nt < 4; nt++) {
            int r = wm + mt * 16 + (lane >> 2);
            int c = wn + nt * 8 + (lane & 3) * 2;
            stg[r * 132 + c]           = acc[mt][nt][0];
            stg[r * 132 + c + 1]       = acc[mt][nt][1];
            stg[(r + 8) * 132 + c]     = acc[mt][nt][2];
            stg[(r + 8) * 132 + c + 1] = acc[mt][nt][3];
        }
    __syncthreads();

    if (MODE == 0) {
        const float sc = g.scale[0];
        for (int e = tid; e < 128 * 128; e += 256) {
            int m = e >> 7, n = e & 127;
            size_t o = ((size_t)b * T_ + m0 + m) * E_ + n0 + n;
            float v = (stg[m * 132 + n] + g.bias[n0 + n] + g.xres[o]) * sc;
            bf16 h = __float2bfloat16(v);
            g.outH[o] = h;
            g.outL[o] = __float2bfloat16(v - __bfloat162float(h));
        }
    } else if (MODE == 1) {
        for (int e = tid; e < 128 * 128; e += 256) {
            int m = e >> 7, n = e & 127;
            g.outF[((size_t)b * T_ + m0 + m) * S_ + n0 + n] = stg[m * 132 + n];
        }
    } else if (MODE == 2) {
        for (int e = tid; e < 128 * 128; e += 256) {
            int m = e >> 7, n = e & 127;
            size_t o = ((size_t)b * T_ + m0 + m) * E_ + n0 + n;
            float v = stg[m * 132 + n];
            bf16 h = __float2bfloat16(v);
            g.outH[o] = h;
            g.outL[o] = __float2bfloat16(v - __bfloat162float(h));
        }
    } else {
        for (int e = tid; e < 128 * 128; e += 256) {
            int n = e >> 7, m = e & 127;   // m fastest -> coalesced transposed store
            size_t o = ((size_t)b * C_ + n0 + n) * T_ + m0 + m;
            g.outF[o] = stg[m * 132 + n] + g.bias[n0 + n] + g.conved[o];
        }
    }
}

// ---------------- aux kernels -----------------------------------------------
__global__ __launch_bounds__(256) void convert_split(const float4* __restrict__ in,
                                                     bf16* __restrict__ oh,
                                                     bf16* __restrict__ ol, size_t n4) {
    size_t i = (size_t)blockIdx.x * 256 + threadIdx.x;
    if (i >= n4) return;
    float4 f = in[i];
    bf16 h0 = __float2bfloat16(f.x), h1 = __float2bfloat16(f.y);
    bf16 h2 = __float2bfloat16(f.z), h3 = __float2bfloat16(f.w);
    ((__nv_bfloat162*)oh)[2 * i]     = {h0, h1};
    ((__nv_bfloat162*)oh)[2 * i + 1] = {h2, h3};
    ((__nv_bfloat162*)ol)[2 * i] =
        {__float2bfloat16(f.x - __bfloat162float(h0)),
         __float2bfloat16(f.y - __bfloat162float(h1))};
    ((__nv_bfloat162*)ol)[2 * i + 1] =
        {__float2bfloat16(f.z - __bfloat162float(h2)),
         __float2bfloat16(f.w - __bfloat162float(h3))};
}

// in: [B][R][C] fp32 -> out: [B][C][R] bf16 hi/lo
__global__ __launch_bounds__(256) void transpose_split(const float* __restrict__ in,
                                                       bf16* __restrict__ oh,
                                                       bf16* __restrict__ ol,
                                                       int R, int C) {
    __shared__ float tile[32][33];
    const int bz = blockIdx.z;
    const float* src = in + (size_t)bz * R * C;
    const size_t ob = (size_t)bz * R * C;
    const int c0 = blockIdx.x * 32, r0 = blockIdx.y * 32;
    const int tx = threadIdx.x & 31, ty = threadIdx.x >> 5;
#pragma unroll
    for (int i = 0; i < 4; i++)
        tile[ty + i * 8][tx] = src[(size_t)(r0 + ty + i * 8) * C + c0 + tx];
    __syncthreads();
#pragma unroll
    for (int i = 0; i < 4; i++) {
        float v = tile[tx][ty + i * 8];
        size_t o = ob + (size_t)(c0 + ty + i * 8) * R + r0 + tx;
        bf16 h = __float2bfloat16(v);
        oh[o] = h;
        ol[o] = __float2bfloat16(v - __bfloat162float(h));
    }
}

__global__ __launch_bounds__(256) void softmax_split(float* __restrict__ att,
                                                     bf16* __restrict__ oh,
                                                     bf16* __restrict__ ol) {
    const size_t rb = (size_t)blockIdx.x * S_;
    float* p = att + rb;
    const int tid = threadIdx.x;
    __shared__ float red[8];

    float v[8];
    float mx = -1e30f;
#pragma unroll
    for (int i = 0; i < 8; i++) { v[i] = p[tid + i * 256]; mx = fmaxf(mx, v[i]); }
#pragma unroll
    for (int o = 16; o; o >>= 1) mx = fmaxf(mx, __shfl_xor_sync(0xffffffffu, mx, o));
    if ((tid & 31) == 0) red[tid >> 5] = mx;
    __syncthreads();
    float bm = red[0];
#pragma unroll
    for (int wi = 1; wi < 8; wi++) bm = fmaxf(bm, red[wi]);
    __syncthreads();

    float sum = 0.f;
#pragma unroll
    for (int i = 0; i < 8; i++) { v[i] = __expf(v[i] - bm); sum += v[i]; }
#pragma unroll
    for (int o = 16; o; o >>= 1) sum += __shfl_xor_sync(0xffffffffu, sum, o);
    if ((tid & 31) == 0) red[tid >> 5] = sum;
    __syncthreads();
    float bs = 0.f;
#pragma unroll
    for (int wi = 0; wi < 8; wi++) bs += red[wi];
    const float inv = 1.f / bs;
#pragma unroll
    for (int i = 0; i < 8; i++) {
        float pv = v[i] * inv;
        size_t o = rb + tid + i * 256;
        att[o] = pv;
        bf16 h = __float2bfloat16(pv);
        oh[o] = h;
        ol[o] = __float2bfloat16(pv - __bfloat162float(h));
    }
}

// ---------------- host -------------------------------------------------------
extern "C" void kernel_launch(void* const* d_in, const int* in_sizes, int n_in,
                              void* d_out, int out_size) {
    (void)in_sizes; (void)n_in; (void)out_size;
    const float* conved   = (const float*)d_in[0];
    const float* enc_conv = (const float*)d_in[1];
    const float* enc_comb = (const float*)d_in[2];
    const float* x        = (const float*)d_in[3];
    const float* scale    = (const float*)d_in[4];
    const float* W_h2e    = (const float*)d_in[5];
    const float* b_h2e    = (const float*)d_in[6];
    const float* W_e2h    = (const float*)d_in[7];
    const float* b_e2h    = (const float*)d_in[8];

    float* attn = (float*)d_out;
    float* out2 = (float*)d_out + (size_t)B_ * T_ * S_;

    bf16 *convT_h, *convT_l, *wh2e_h, *wh2e_l, *encK_h, *encK_l, *comb_h, *comb_l;
    bf16 *attn_h, *attn_l, *encVT_h, *encVT_l, *attd_h, *attd_l, *we2h_h, *we2h_l;
    cudaGetSymbolAddress((void**)&convT_h, g_convT_h);
    cudaGetSymbolAddress((void**)&convT_l, g_convT_l);
    cudaGetSymbolAddress((void**)&wh2e_h,  g_wh2e_h);
    cudaGetSymbolAddress((void**)&wh2e_l,  g_wh2e_l);
    cudaGetSymbolAddress((void**)&encK_h,  g_encK_h);
    cudaGetSymbolAddress((void**)&encK_l,  g_encK_l);
    cudaGetSymbolAddress((void**)&comb_h,  g_comb_h);
    cudaGetSymbolAddress((void**)&comb_l,  g_comb_l);
    cudaGetSymbolAddress((void**)&attn_h,  g_attn_h);
    cudaGetSymbolAddress((void**)&attn_l,  g_attn_l);
    cudaGetSymbolAddress((void**)&encVT_h, g_encVT_h);
    cudaGetSymbolAddress((void**)&encVT_l, g_encVT_l);
    cudaGetSymbolAddress((void**)&attd_h,  g_attd_h);
    cudaGetSymbolAddress((void**)&attd_l,  g_attd_l);
    cudaGetSymbolAddress((void**)&we2h_h,  g_we2h_h);
    cudaGetSymbolAddress((void**)&we2h_l,  g_we2h_l);

    cudaFuncSetAttribute(mma_gemm<0>, cudaFuncAttributeMaxDynamicSharedMemorySize, SMEM_BYTES);
    cudaFuncSetAttribute(mma_gemm<1>, cudaFuncAttributeMaxDynamicSharedMemorySize, SMEM_BYTES);
    cudaFuncSetAttribute(mma_gemm<2>, cudaFuncAttributeMaxDynamicSharedMemorySize, SMEM_BYTES);
    cudaFuncSetAttribute(mma_gemm<3>, cudaFuncAttributeMaxDynamicSharedMemorySize, SMEM_BYTES);

    // preprocessing
    transpose_split<<<dim3(T_/32, C_/32, B_), 256>>>(conved, convT_h, convT_l, C_, T_);
    transpose_split<<<dim3(E_/32, S_/32, B_), 256>>>(enc_comb, encVT_h, encVT_l, S_, E_);
    {
        size_t n4 = (size_t)E_ * C_ / 4;
        convert_split<<<(unsigned)((n4 + 255) / 256), 256>>>((const float4*)W_h2e, wh2e_h, wh2e_l, n4);
        convert_split<<<(unsigned)((n4 + 255) / 256), 256>>>((const float4*)W_e2h, we2h_h, we2h_l, n4);
        size_t m4 = (size_t)B_ * S_ * E_ / 4;
        convert_split<<<(unsigned)((m4 + 255) / 256), 256>>>((const float4*)enc_conv, encK_h, encK_l, m4);
    }

    GemmArgs a{};

    // Stage 1: comb = (convT @ W_h2e^T + b + x) * scale -> bf16 hi/lo
    a = GemmArgs{convT_h, convT_l, wh2e_h, wh2e_l,
                 (long)T_ * C_, 0L, C_, C_, C_ / 64,
                 nullptr, comb_h, comb_l, b_h2e, x, scale, nullptr};
    mma_gemm<0><<<dim3(T_/128, E_/128, B_), 256, SMEM_BYTES>>>(a);

    // Stage 2: energy = comb @ enc_conved^T -> fp32 in d_out
    a = GemmArgs{comb_h, comb_l, encK_h, encK_l,
                 (long)T_ * E_, (long)S_ * E_, E_, E_, E_ / 64,
                 attn, nullptr, nullptr, nullptr, nullptr, nullptr, nullptr};
    mma_gemm<1><<<dim3(T_/128, S_/128, B_), 256, SMEM_BYTES>>>(a);

    // Stage 3: softmax in place + bf16 hi/lo
    softmax_split<<<B_ * T_, 256>>>(attn, attn_h, attn_l);

    // Stage 4: attended = attn @ enc_combined (B pre-transposed [E,S]) -> hi/lo
    a = GemmArgs{attn_h, attn_l, encVT_h, encVT_l,
                 (long)T_ * S_, (long)E_ * S_, S_, S_, S_ / 64,
                 nullptr, attd_h, attd_l, nullptr, nullptr, nullptr, nullptr};
    mma_gemm<2><<<dim3(T_/128, E_/128, B_), 256, SMEM_BYTES>>>(a);

    // Stage 5: out2[b,c,t] = attd @ W_e2h^T + b_e2h + conved
    a = GemmArgs{attd_h, attd_l, we2h_h, we2h_l,
                 (long)T_ * E_, 0L, E_, E_, E_ / 64,
                 out2, nullptr, nullptr, b_e2h, nullptr, nullptr, conved};
    mma_gemm<3><<<dim3(T_/128, C_/128, B_), 256, SMEM_BYTES>>>(a);
}